// round 16
// baseline (speedup 1.0000x reference)
#include <cuda_runtime.h>
#include <math.h>

#define BATCH 16
#define NCLS  20
#define NSEL  2400
#define KTOP  100
#define NPRE  1000
#define CHUNK 128     // target candidates per NMS chunk
#define CHCAP 224     // capacity incl. 16-bit pivot ties (margin 96)

// PDL: block until the preceding grid (stream order) completes, with full
// memory visibility.
__device__ __forceinline__ void pdl_wait() {
    asm volatile("griddepcontrol.wait;" ::: "memory");
}

// Warp-aggregated histogram add: lanes with equal bin values aggregate into a
// single atomicAdd by the group leader. MUST be called warp-convergently.
// 'active' lanes contribute; inactive lanes form singleton groups and skip.
__device__ __forceinline__ void hist_add(int* hist, unsigned bin, bool active, int lane) {
    unsigned key = active ? bin : (0x100u + (unsigned)lane);
    unsigned mm = __match_any_sync(0xffffffffu, key);
    if (active && lane == (__ffs(mm) - 1))
        atomicAdd(&hist[bin], __popc(mm));
}

// ---------------- scratch (device globals; no allocations allowed) ----------
__device__ int      g_sel[BATCH * 2 * NPRE];
__device__ float4   g_boxes[BATCH * NSEL];
__device__ unsigned g_keysT[BATCH * NCLS * NSEL];   // [b][c][s] f2u(sigmoid) keys
__device__ float    g_selscore[BATCH * NCLS * KTOP];
__device__ int      g_selidx[BATCH * NCLS * KTOP];

__device__ __forceinline__ unsigned f2u(float f) {
    unsigned u = __float_as_uint(f);
    return (u & 0x80000000u) ? ~u : (u | 0x80000000u);
}
__device__ __forceinline__ float u2f(unsigned h) {
    return __uint_as_float((h & 0x80000000u) ? (h ^ 0x80000000u) : ~h);
}

// ---------- K1: fused max-logit + histogram-select top-1000 per (b, level) --
__global__ void __launch_bounds__(1024) k_select(const float* __restrict__ cls0,
                                                 const float* __restrict__ cls1) {
    __shared__ int hist[256];
    __shared__ int s_bin, s_high;
    __shared__ int c1, c2;
    int b = blockIdx.x >> 1, l = blockIdx.x & 1;
    int n = l ? 1600 : 6400;
    const float* src = l ? (cls1 + (size_t)b * 1600 * NCLS)
                         : (cls0 + (size_t)b * 6400 * NCLS);
    int t = threadIdx.x, lane = t & 31;
    unsigned kreg[7];
    int nk = l ? 2 : 7;
    for (int j = 0; j < nk; j++) {
        int i = j * 1024 + t;
        unsigned key = 0u;
        if (i < n) {
            const float4* q = (const float4*)(src + (size_t)i * NCLS);
            float4 v0 = q[0], v1 = q[1], v2 = q[2], v3 = q[3], v4 = q[4];
            float m = fmaxf(fmaxf(fmaxf(v0.x, v0.y), fmaxf(v0.z, v0.w)),
                            fmaxf(fmaxf(v1.x, v1.y), fmaxf(v1.z, v1.w)));
            m = fmaxf(m, fmaxf(fmaxf(v2.x, v2.y), fmaxf(v2.z, v2.w)));
            m = fmaxf(m, fmaxf(fmaxf(v3.x, v3.y), fmaxf(v3.z, v3.w)));
            m = fmaxf(m, fmaxf(fmaxf(v4.x, v4.y), fmaxf(v4.z, v4.w)));
            key = f2u(m);
        }
        kreg[j] = key;
    }
    if (t == 0) { c1 = 0; c2 = 0; }

    unsigned prefix = 0;
    int needed = NPRE, G = 0;
    for (int level = 0; level < 4; level++) {
        int shift = 24 - 8 * level;
        if (t < 256) hist[t] = 0;
        __syncthreads();
        for (int j = 0; j < nk; j++) {
            int i = j * 1024 + t;
            unsigned k = kreg[j];
            bool match = (i < n) &&
                (level == 0 || (k >> (shift + 8)) == (prefix >> (shift + 8)));
            hist_add(hist, (k >> shift) & 255, match, lane);
        }
        __syncthreads();
        if (t < 32) {
            int s = 0;
            #pragma unroll
            for (int q = 0; q < 8; q++) s += hist[t * 8 + q];
            int suf = s;
            #pragma unroll
            for (int off = 1; off < 32; off <<= 1) {
                int v = __shfl_down_sync(0xffffffffu, suf, off);
                if (t + off < 32) suf += v;
            }
            int suf_next = suf - s;
            if (suf >= needed && suf_next < needed) {
                int cum = suf_next;
                #pragma unroll
                for (int q = 7; q >= 0; q--) {
                    int h = hist[t * 8 + q];
                    if (cum + h >= needed) { s_bin = t * 8 + q; s_high = cum; break; }
                    cum += h;
                }
            }
        }
        __syncthreads();
        prefix |= ((unsigned)s_bin) << shift;
        G += s_high;
        needed -= s_high;
        __syncthreads();
    }
    unsigned v = prefix;

    int* out = g_sel + (b * 2 + l) * NPRE;
    for (int j = 0; j < nk; j++) {
        int i = j * 1024 + t;
        if (i < n && kreg[j] > v) out[atomicAdd(&c1, 1)] = i;
    }
    for (int j = 0; j < nk; j++) {
        int i = j * 1024 + t;
        if (i < n && kreg[j] == v) { int p = atomicAdd(&c2, 1); if (G + p < NPRE) out[G + p] = i; }
    }
}

// ---------------- K2: gather survivors, keys + DFL boxes (coalesced) --------
__global__ void __launch_bounds__(256) k_gather(
        const float* __restrict__ cls0, const float* __restrict__ cls1,
        const float* __restrict__ cls2,
        const float* __restrict__ bb0, const float* __restrict__ bb1,
        const float* __restrict__ bb2) {
    int b = blockIdx.x / 10, sb = blockIdx.x % 10;
    int t = threadIdx.x;
    int s = sb * 256 + t;
    pdl_wait();   // g_sel must be complete (k_select)
    if (s >= NSEL) return;
    const float* cls; const float* bb; int anchor; int w; float stride;
    if (s < 1000) {
        anchor = g_sel[(b * 2 + 0) * NPRE + s]; w = 80; stride = 8.f;
        cls = cls0 + ((size_t)b * 6400 + anchor) * NCLS;
        bb  = bb0 + ((size_t)b * 6400 + anchor) * 32;
    } else if (s < 2000) {
        anchor = g_sel[(b * 2 + 1) * NPRE + (s - 1000)]; w = 40; stride = 16.f;
        cls = cls1 + ((size_t)b * 1600 + anchor) * NCLS;
        bb  = bb1 + ((size_t)b * 1600 + anchor) * 32;
    } else {
        anchor = s - 2000; w = 20; stride = 32.f;
        cls = cls2 + ((size_t)b * 400 + anchor) * NCLS;
        bb  = bb2 + ((size_t)b * 400 + anchor) * 32;
    }
    float py = ((float)(anchor / w) + 0.5f) * stride;
    float px = ((float)(anchor % w) + 0.5f) * stride;
    const float4* bbv = (const float4*)bb;
    float d[4];
    #pragma unroll
    for (int g = 0; g < 4; g++) {
        float4 lo = bbv[g * 2], hi = bbv[g * 2 + 1];
        float x[8] = {lo.x, lo.y, lo.z, lo.w, hi.x, hi.y, hi.z, hi.w};
        float m = -INFINITY;
        #pragma unroll
        for (int k = 0; k < 8; k++) m = fmaxf(m, x[k]);
        float den = 0.f, num = 0.f;
        #pragma unroll
        for (int k = 0; k < 8; k++) { float e = expf(x[k] - m); den += e; num += e * (float)k; }
        d[g] = num / den * stride;
    }
    float y1 = fminf(fmaxf(py - d[0], 0.f), 640.f);
    float x1 = fminf(fmaxf(px - d[1], 0.f), 640.f);
    float y2 = fminf(fmaxf(py + d[2], 0.f), 640.f);
    float x2 = fminf(fmaxf(px + d[3], 0.f), 640.f);
    g_boxes[b * NSEL + s] = make_float4(y1, x1, y2, x2);
    const float4* clv = (const float4*)cls;
    unsigned* kb = g_keysT + (size_t)b * NCLS * NSEL + s;
    #pragma unroll
    for (int q = 0; q < 5; q++) {
        float4 lv = clv[q];
        kb[(q * 4 + 0) * NSEL] = f2u(1.f / (1.f + expf(-lv.x)));
        kb[(q * 4 + 1) * NSEL] = f2u(1.f / (1.f + expf(-lv.y)));
        kb[(q * 4 + 2) * NSEL] = f2u(1.f / (1.f + expf(-lv.z)));
        kb[(q * 4 + 3) * NSEL] = f2u(1.f / (1.f + expf(-lv.w)));
    }
}

// ---------------- K3: chunked NMS, tile-incremental suppression -------------
__global__ void __launch_bounds__(256) k_nms() {
    __shared__ int hist[256];
    __shared__ int s_bin, s_high;
    __shared__ int sL, s_ns;
    __shared__ unsigned s_accmask;
    __shared__ unsigned long long ukey[CHCAP];
    __shared__ unsigned long long skey[CHCAP];
    __shared__ float4 cb[CHCAP];
    __shared__ float  car[CHCAP];
    __shared__ float4 ab[KTOP];
    __shared__ float  aar_[KTOP];
    __shared__ unsigned wsup[8];
    __shared__ unsigned mat32[32];

    int b = blockIdx.x / NCLS, c = blockIdx.x % NCLS;
    int t = threadIdx.x, lane = t & 31, wid = t >> 5;
    const unsigned* keys  = g_keysT + ((size_t)b * NCLS + c) * NSEL;
    const float4*   boxes = g_boxes + b * NSEL;
    float* selS = g_selscore + ((size_t)b * NCLS + c) * KTOP;
    int*   selI = g_selidx + ((size_t)b * NCLS + c) * KTOP;

    pdl_wait();   // g_keysT / g_boxes must be complete (k_gather)

    unsigned kreg[10];
    #pragma unroll
    for (int j = 0; j < 10; j++) {
        int i = j * 256 + t;
        kreg[j] = (i < NSEL) ? keys[i] : 0u;   // real keys always >= 0x80000000
    }

    int ns = 0, remaining = NSEL;

    while (ns < KTOP && remaining > 0) {
        int M = remaining < CHUNK ? remaining : CHUNK;

        // ---- two-level 8-bit histogram pivot (warp-aggregated adds) ---------
        unsigned pivot = 0;
        int needed = M;
        #pragma unroll
        for (int level = 0; level < 2; level++) {
            int shift = 24 - 8 * level;
            hist[t] = 0;
            if (t == 0) { s_bin = 0; s_high = 0; }
            __syncthreads();
            #pragma unroll
            for (int j = 0; j < 10; j++) {
                unsigned k = kreg[j];
                bool match = (k != 0u) &&
                    (level == 0 || (k >> 24) == (pivot >> 24));
                hist_add(hist, (k >> shift) & 255, match, lane);
            }
            __syncthreads();
            if (t < 32) {
                int s = 0;
                #pragma unroll
                for (int q = 0; q < 8; q++) s += hist[t * 8 + q];
                int suf = s;
                #pragma unroll
                for (int off = 1; off < 32; off <<= 1) {
                    int v = __shfl_down_sync(0xffffffffu, suf, off);
                    if (t + off < 32) suf += v;
                }
                int suf_next = suf - s;
                if (suf >= needed && suf_next < needed) {
                    int cum = suf_next;
                    #pragma unroll
                    for (int q = 7; q >= 0; q--) {
                        int h = hist[t * 8 + q];
                        if (cum + h >= needed) { s_bin = t * 8 + q; s_high = cum; break; }
                        cum += h;
                    }
                }
            }
            __syncthreads();
            pivot |= ((unsigned)s_bin) << shift;
            needed -= s_high;
            __syncthreads();
        }

        // ---- compact all keys >= pivot (zeroed keys are < pivot) -----------
        if (t == 0) sL = 0;
        __syncthreads();
        #pragma unroll
        for (int j = 0; j < 10; j++) {
            unsigned k = kreg[j];
            if (k >= pivot) {
                int p = atomicAdd(&sL, 1);
                if (p < CHCAP)
                    ukey[p] = ((unsigned long long)k << 32) | (unsigned)(4095 - (j * 256 + t));
            }
        }
        __syncthreads();
        int Ltrue = sL;
        int L = Ltrue < CHCAP ? Ltrue : CHCAP;

        // ---- rank sort: only threads t < L rank (idle warps branch around) --
        if (t < L) {
            unsigned long long k0 = ukey[t];
            int r0 = 0;
            for (int q = 0; q < L; q++) r0 += (ukey[q] > k0);   // broadcast LDS
            skey[r0] = k0;   // ranks are a permutation of [0,L)
        }
        __syncthreads();

        // ---- gather boxes in sorted order -----------------------------------
        if (t < L) {
            int i = 4095 - (int)(unsigned)(skey[t] & 0xffffffffull);
            float4 bx = boxes[i];
            cb[t] = bx;
            car[t] = (bx.z - bx.x) * (bx.w - bx.y);
        }
        __syncthreads();

        // ---- tile loop -------------------------------------------------------
        for (int p0 = 0; p0 < L && ns < KTOP; p0 += 32) {
            int nt = L - p0; if (nt > 32) nt = 32;

            // Phase A: suppression by accepted (lane = candidate; warp strides accepted)
            bool sup = false;
            float4 bj = make_float4(0.f, 0.f, 0.f, 0.f); float aj = 0.f;
            bool jok = lane < nt;
            if (jok) { bj = cb[p0 + lane]; aj = car[p0 + lane]; }
            for (int a = wid; a < ns; a += 8) {
                float4 ba = ab[a];
                float yy1 = fmaxf(ba.x, bj.x);
                float xx1 = fmaxf(ba.y, bj.y);
                float yy2 = fminf(ba.z, bj.z);
                float xx2 = fminf(ba.w, bj.w);
                float inter = fmaxf(yy2 - yy1, 0.f) * fmaxf(xx2 - xx1, 0.f);
                float iou = inter / (aar_[a] + aj - inter + 1e-9f);
                sup |= (jok && iou > 0.5f);
            }
            unsigned bal = __ballot_sync(0xffffffffu, sup);
            if (lane == 0) wsup[wid] = bal;

            // Phase B: intra-tile triangular matrix, warp w rows i = w, w+8, ...
            #pragma unroll
            for (int ii = 0; ii < 4; ii++) {
                int i = wid + ii * 8;
                bool s = false;
                if (i < nt) {
                    float4 bi = cb[p0 + i];
                    float ai = car[p0 + i];
                    if (jok && lane > i) {
                        float yy1 = fmaxf(bi.x, bj.x);
                        float xx1 = fmaxf(bi.y, bj.y);
                        float yy2 = fminf(bi.z, bj.z);
                        float xx2 = fminf(bi.w, bj.w);
                        float inter = fmaxf(yy2 - yy1, 0.f) * fmaxf(xx2 - xx1, 0.f);
                        float iou = inter / (ai + aj - inter + 1e-9f);
                        s = iou > 0.5f;
                    }
                }
                unsigned mb = __ballot_sync(0xffffffffu, s);
                if (lane == 0 && i < 32) mat32[i] = mb;
            }
            __syncthreads();

            // Phase C: serial bit-scan (thread 0)
            if (t == 0) {
                unsigned alive = ~(wsup[0] | wsup[1] | wsup[2] | wsup[3] |
                                   wsup[4] | wsup[5] | wsup[6] | wsup[7]);
                if (nt < 32) alive &= ((1u << nt) - 1u);
                unsigned accm = 0; int n2 = ns;
                while (alive && n2 < KTOP) {
                    int i = __ffs(alive) - 1;
                    accm |= (1u << i);
                    n2++;
                    alive &= ~(1u << i);
                    alive &= ~mat32[i];
                }
                s_accmask = accm; s_ns = n2;
            }
            __syncthreads();

            // Phase D: parallel append of accepted
            unsigned accm = s_accmask;
            if (t < 32 && ((accm >> t) & 1u)) {
                int r = ns + __popc(accm & ((1u << t) - 1u));
                unsigned long long key = skey[p0 + t];
                selS[r] = u2f((unsigned)(key >> 32));
                selI[r] = 4095 - (int)(unsigned)(key & 0xffffffffull);
                ab[r] = cb[p0 + t];
                aar_[r] = car[p0 + t];
            }
            __syncthreads();
            ns = s_ns;
        }

        // ---- zero consumed keys; update remaining ----------------------------
        #pragma unroll
        for (int j = 0; j < 10; j++)
            if (kreg[j] >= pivot) kreg[j] = 0u;
        remaining -= Ltrue;
    }
    // fewer than KTOP survivors: reference yields argmax over all -inf
    for (int r = ns + t; r < KTOP; r += 256) { selS[r] = -INFINITY; selI[r] = 0; }
}

// -------- K4: per-batch final top-100 (2-level histogram) + masking ---------
__global__ void __launch_bounds__(256) k_final(float* __restrict__ out) {
    __shared__ int hist[256];
    __shared__ int s_bin, s_high;
    __shared__ int sL;
    __shared__ unsigned long long fukey[384];
    __shared__ unsigned long long fskey[384];
    const int N2 = NCLS * KTOP;   // 2000
    int b = blockIdx.x, t = threadIdx.x, lane = t & 31;
    const float* sel = g_selscore + (size_t)b * N2;

    pdl_wait();   // g_selscore/g_selidx must be complete (k_nms)

    unsigned fk[8];
    #pragma unroll
    for (int j = 0; j < 8; j++) {
        int i = j * 256 + t;
        unsigned k = 0u;
        if (i < N2) {
            float s = sel[i];
            if (isfinite(s)) k = f2u(s);
        }
        fk[j] = k;
    }
    // two-level histogram pivot for rank KTOP (warp-aggregated adds)
    unsigned pivot = 0;
    int needed = KTOP;
    #pragma unroll
    for (int level = 0; level < 2; level++) {
        int shift = 24 - 8 * level;
        hist[t] = 0;
        if (t == 0) { s_bin = 0; s_high = 0; }
        __syncthreads();
        #pragma unroll
        for (int j = 0; j < 8; j++) {
            unsigned k = fk[j];
            bool match = (k != 0u) && (level == 0 || (k >> 24) == (pivot >> 24));
            hist_add(hist, (k >> shift) & 255, match, lane);
        }
        __syncthreads();
        if (t < 32) {
            int s = 0;
            #pragma unroll
            for (int q = 0; q < 8; q++) s += hist[t * 8 + q];
            int suf = s;
            #pragma unroll
            for (int off = 1; off < 32; off <<= 1) {
                int v = __shfl_down_sync(0xffffffffu, suf, off);
                if (t + off < 32) suf += v;
            }
            int suf_next = suf - s;
            if (suf >= needed && suf_next < needed) {
                int cum = suf_next;
                #pragma unroll
                for (int q = 7; q >= 0; q--) {
                    int h = hist[t * 8 + q];
                    if (cum + h >= needed) { s_bin = t * 8 + q; s_high = cum; break; }
                    cum += h;
                }
            }
        }
        __syncthreads();
        pivot |= ((unsigned)s_bin) << shift;
        needed -= s_high;
        __syncthreads();
    }
    // compact finite keys >= pivot (prefix-complete incl. ties)
    if (t == 0) sL = 0;
    __syncthreads();
    #pragma unroll
    for (int j = 0; j < 8; j++) {
        int i = j * 256 + t;
        unsigned k = fk[j];
        if (k != 0u && k >= pivot) {
            int p = atomicAdd(&sL, 1);
            if (p < 384) fukey[p] = ((unsigned long long)k << 32) | (unsigned)(4095 - i);
        }
    }
    for (int p = t; p < 384; p += 256) fskey[p] = 0ull;
    __syncthreads();
    int L2 = sL < 384 ? sL : 384;
    {
        unsigned long long k0 = 0ull, k1 = 0ull;
        int p0i = t, p1i = t + 256;
        if (p0i < L2) k0 = fukey[p0i];
        if (p1i < L2) k1 = fukey[p1i];
        int r0 = 0, r1 = 0;
        for (int q = 0; q < L2; q++) {
            unsigned long long kq = fukey[q];
            r0 += (kq > k0);
            r1 += (kq > k1);
        }
        __syncthreads();
        if (p0i < L2 && r0 < 384) fskey[r0] = k0;
        if (p1i < L2 && r1 < 384) fskey[r1] = k1;
    }
    __syncthreads();
    if (t < KTOP) {
        unsigned long long key = fskey[t];
        float* o = out + ((size_t)b * KTOP + t) * 6;
        float vals[6] = {0.f, 0.f, 0.f, 0.f, 0.f, 0.f};
        if (key != 0ull) {
            int i = 4095 - (int)(unsigned)(key & 0xffffffffull);
            int cc = i / KTOP, kk = i % KTOP;
            float s = g_selscore[((size_t)b * NCLS + cc) * KTOP + kk];
            if (isfinite(s) && s > 0.3f) {
                int idx = g_selidx[((size_t)b * NCLS + cc) * KTOP + kk];
                float4 bx = g_boxes[b * NSEL + idx];
                vals[0] = bx.x; vals[1] = bx.y; vals[2] = bx.z; vals[3] = bx.w;
                vals[4] = s; vals[5] = (float)cc;
            }
        }
        #pragma unroll
        for (int q = 0; q < 6; q++) o[q] = vals[q];
    }
}

// ---------------- launch (PDL-chained) ---------------------------------------
static void launch_pdl(void* func, dim3 grid, dim3 block, void** args) {
    cudaLaunchConfig_t cfg = {};
    cfg.gridDim = grid;
    cfg.blockDim = block;
    cfg.dynamicSmemBytes = 0;
    cfg.stream = 0;
    cudaLaunchAttribute attr[1];
    attr[0].id = cudaLaunchAttributeProgrammaticStreamSerialization;
    attr[0].val.programmaticStreamSerializationAllowed = 1;
    cfg.attrs = attr;
    cfg.numAttrs = 1;
    cudaLaunchKernelExC(&cfg, func, args);
}

extern "C" void kernel_launch(void* const* d_in, const int* in_sizes, int n_in,
                              void* d_out, int out_size) {
    const float *cls0 = 0, *cls1 = 0, *cls2 = 0, *bb0 = 0, *bb1 = 0, *bb2 = 0;
    for (int i = 0; i < n_in; i++) {
        const float* p = (const float*)d_in[i];
        switch (in_sizes[i]) {
            case 2048000: cls0 = p; break;  // 16*6400*20
            case 3276800: bb0  = p; break;  // 16*6400*32
            case 512000:  cls1 = p; break;  // 16*1600*20
            case 819200:  bb1  = p; break;  // 16*1600*32
            case 128000:  cls2 = p; break;  // 16*400*20
            case 204800:  bb2  = p; break;  // 16*400*32
            default: break;                 // origin_shapes (unused by reference)
        }
    }
    k_select<<<32, 1024>>>(cls0, cls1);

    {
        void* args[6] = {&cls0, &cls1, &cls2, &bb0, &bb1, &bb2};
        launch_pdl((void*)k_gather, dim3(BATCH * 10), dim3(256), args);
    }
    {
        void* args[1] = {nullptr};
        launch_pdl((void*)k_nms, dim3(BATCH * NCLS), dim3(256), args);
    }
    {
        float* outp = (float*)d_out;
        void* args[1] = {&outp};
        launch_pdl((void*)k_final, dim3(BATCH), dim3(256), args);
    }
}

// round 17
// speedup vs baseline: 1.6192x; 1.6192x over previous
#include <cuda_runtime.h>
#include <math.h>

#define BATCH 16
#define NCLS  20
#define NSEL  2400
#define KTOP  100
#define NPRE  1000
#define CHUNK 128     // target candidates per NMS chunk
#define CHCAP 224     // capacity incl. 16-bit pivot ties (margin 96)

// PDL: block until the preceding grid (stream order) completes, with full
// memory visibility. Used by kernels launched with programmatic stream
// serialization so their launch latency overlaps upstream execution.
__device__ __forceinline__ void pdl_wait() {
    asm volatile("griddepcontrol.wait;" ::: "memory");
}

// ---------------- scratch (device globals; no allocations allowed) ----------
__device__ int      g_sel[BATCH * 2 * NPRE];
__device__ float4   g_boxes[BATCH * NSEL];
__device__ unsigned g_keysT[BATCH * NCLS * NSEL];   // [b][c][s] f2u(sigmoid) keys
__device__ float    g_selscore[BATCH * NCLS * KTOP];
__device__ int      g_selidx[BATCH * NCLS * KTOP];

__device__ __forceinline__ unsigned f2u(float f) {
    unsigned u = __float_as_uint(f);
    return (u & 0x80000000u) ? ~u : (u | 0x80000000u);
}
__device__ __forceinline__ float u2f(unsigned h) {
    return __uint_as_float((h & 0x80000000u) ? (h ^ 0x80000000u) : ~h);
}

// ---------- K1: fused max-logit + histogram-select top-1000 per (b, level) --
__global__ void __launch_bounds__(1024) k_select(const float* __restrict__ cls0,
                                                 const float* __restrict__ cls1) {
    __shared__ int hist[256];
    __shared__ int s_bin, s_high;
    __shared__ int c1, c2;
    int b = blockIdx.x >> 1, l = blockIdx.x & 1;
    int n = l ? 1600 : 6400;
    const float* src = l ? (cls1 + (size_t)b * 1600 * NCLS)
                         : (cls0 + (size_t)b * 6400 * NCLS);
    int t = threadIdx.x;
    unsigned kreg[7];
    int nk = l ? 2 : 7;
    for (int j = 0; j < nk; j++) {
        int i = j * 1024 + t;
        unsigned key = 0u;
        if (i < n) {
            const float4* q = (const float4*)(src + (size_t)i * NCLS);
            float4 v0 = q[0], v1 = q[1], v2 = q[2], v3 = q[3], v4 = q[4];
            float m = fmaxf(fmaxf(fmaxf(v0.x, v0.y), fmaxf(v0.z, v0.w)),
                            fmaxf(fmaxf(v1.x, v1.y), fmaxf(v1.z, v1.w)));
            m = fmaxf(m, fmaxf(fmaxf(v2.x, v2.y), fmaxf(v2.z, v2.w)));
            m = fmaxf(m, fmaxf(fmaxf(v3.x, v3.y), fmaxf(v3.z, v3.w)));
            m = fmaxf(m, fmaxf(fmaxf(v4.x, v4.y), fmaxf(v4.z, v4.w)));
            key = f2u(m);
        }
        kreg[j] = key;
    }
    if (t == 0) { c1 = 0; c2 = 0; }

    unsigned prefix = 0;
    int needed = NPRE, G = 0;
    for (int level = 0; level < 4; level++) {
        int shift = 24 - 8 * level;
        if (t < 256) hist[t] = 0;
        __syncthreads();
        for (int j = 0; j < nk; j++) {
            int i = j * 1024 + t;
            unsigned k = kreg[j];
            bool match = (i < n) &&
                (level == 0 || (k >> (shift + 8)) == (prefix >> (shift + 8)));
            if (match) atomicAdd(&hist[(k >> shift) & 255], 1);
        }
        __syncthreads();
        if (t < 32) {
            int s = 0;
            #pragma unroll
            for (int q = 0; q < 8; q++) s += hist[t * 8 + q];
            int suf = s;
            #pragma unroll
            for (int off = 1; off < 32; off <<= 1) {
                int v = __shfl_down_sync(0xffffffffu, suf, off);
                if (t + off < 32) suf += v;
            }
            int suf_next = suf - s;
            if (suf >= needed && suf_next < needed) {
                int cum = suf_next;
                #pragma unroll
                for (int q = 7; q >= 0; q--) {
                    int h = hist[t * 8 + q];
                    if (cum + h >= needed) { s_bin = t * 8 + q; s_high = cum; break; }
                    cum += h;
                }
            }
        }
        __syncthreads();
        prefix |= ((unsigned)s_bin) << shift;
        G += s_high;
        needed -= s_high;
        __syncthreads();
    }
    unsigned v = prefix;

    int* out = g_sel + (b * 2 + l) * NPRE;
    for (int j = 0; j < nk; j++) {
        int i = j * 1024 + t;
        if (i < n && kreg[j] > v) out[atomicAdd(&c1, 1)] = i;
    }
    for (int j = 0; j < nk; j++) {
        int i = j * 1024 + t;
        if (i < n && kreg[j] == v) { int p = atomicAdd(&c2, 1); if (G + p < NPRE) out[G + p] = i; }
    }
}

// ---------------- K2: gather survivors, keys + DFL boxes (coalesced) --------
// Per-thread key values never cross threads; store directly from registers
// (stores are coalesced across t for each class row).
__global__ void __launch_bounds__(256) k_gather(
        const float* __restrict__ cls0, const float* __restrict__ cls1,
        const float* __restrict__ cls2,
        const float* __restrict__ bb0, const float* __restrict__ bb1,
        const float* __restrict__ bb2) {
    int b = blockIdx.x / 10, sb = blockIdx.x % 10;
    int t = threadIdx.x;
    int s = sb * 256 + t;
    pdl_wait();   // g_sel must be complete (k_select)
    if (s >= NSEL) return;
    const float* cls; const float* bb; int anchor; int w; float stride;
    if (s < 1000) {
        anchor = g_sel[(b * 2 + 0) * NPRE + s]; w = 80; stride = 8.f;
        cls = cls0 + ((size_t)b * 6400 + anchor) * NCLS;
        bb  = bb0 + ((size_t)b * 6400 + anchor) * 32;
    } else if (s < 2000) {
        anchor = g_sel[(b * 2 + 1) * NPRE + (s - 1000)]; w = 40; stride = 16.f;
        cls = cls1 + ((size_t)b * 1600 + anchor) * NCLS;
        bb  = bb1 + ((size_t)b * 1600 + anchor) * 32;
    } else {
        anchor = s - 2000; w = 20; stride = 32.f;
        cls = cls2 + ((size_t)b * 400 + anchor) * NCLS;
        bb  = bb2 + ((size_t)b * 400 + anchor) * 32;
    }
    float py = ((float)(anchor / w) + 0.5f) * stride;
    float px = ((float)(anchor % w) + 0.5f) * stride;
    const float4* bbv = (const float4*)bb;
    float d[4];
    #pragma unroll
    for (int g = 0; g < 4; g++) {
        float4 lo = bbv[g * 2], hi = bbv[g * 2 + 1];
        float x[8] = {lo.x, lo.y, lo.z, lo.w, hi.x, hi.y, hi.z, hi.w};
        float m = -INFINITY;
        #pragma unroll
        for (int k = 0; k < 8; k++) m = fmaxf(m, x[k]);
        float den = 0.f, num = 0.f;
        #pragma unroll
        for (int k = 0; k < 8; k++) { float e = expf(x[k] - m); den += e; num += e * (float)k; }
        d[g] = num / den * stride;
    }
    float y1 = fminf(fmaxf(py - d[0], 0.f), 640.f);
    float x1 = fminf(fmaxf(px - d[1], 0.f), 640.f);
    float y2 = fminf(fmaxf(py + d[2], 0.f), 640.f);
    float x2 = fminf(fmaxf(px + d[3], 0.f), 640.f);
    g_boxes[b * NSEL + s] = make_float4(y1, x1, y2, x2);
    const float4* clv = (const float4*)cls;
    unsigned* kb = g_keysT + (size_t)b * NCLS * NSEL + s;
    #pragma unroll
    for (int q = 0; q < 5; q++) {
        float4 lv = clv[q];
        kb[(q * 4 + 0) * NSEL] = f2u(1.f / (1.f + expf(-lv.x)));
        kb[(q * 4 + 1) * NSEL] = f2u(1.f / (1.f + expf(-lv.y)));
        kb[(q * 4 + 2) * NSEL] = f2u(1.f / (1.f + expf(-lv.z)));
        kb[(q * 4 + 3) * NSEL] = f2u(1.f / (1.f + expf(-lv.w)));
    }
}

// ---------------- K3: chunked NMS, tile-incremental suppression -------------
__global__ void __launch_bounds__(256) k_nms() {
    __shared__ int hist[256];
    __shared__ int s_bin, s_high;
    __shared__ int sL, s_ns;
    __shared__ unsigned s_accmask;
    __shared__ unsigned long long ukey[CHCAP];
    __shared__ unsigned long long skey[CHCAP];
    __shared__ float4 cb[CHCAP];
    __shared__ float  car[CHCAP];
    __shared__ float4 ab[KTOP];
    __shared__ float  aar_[KTOP];
    __shared__ unsigned wsup[8];
    __shared__ unsigned mat32[32];

    int b = blockIdx.x / NCLS, c = blockIdx.x % NCLS;
    int t = threadIdx.x, lane = t & 31, wid = t >> 5;
    const unsigned* keys  = g_keysT + ((size_t)b * NCLS + c) * NSEL;
    const float4*   boxes = g_boxes + b * NSEL;
    float* selS = g_selscore + ((size_t)b * NCLS + c) * KTOP;
    int*   selI = g_selidx + ((size_t)b * NCLS + c) * KTOP;

    pdl_wait();   // g_keysT / g_boxes must be complete (k_gather)

    unsigned kreg[10];
    #pragma unroll
    for (int j = 0; j < 10; j++) {
        int i = j * 256 + t;
        kreg[j] = (i < NSEL) ? keys[i] : 0u;   // real keys always >= 0x80000000
    }

    int ns = 0, remaining = NSEL;

    while (ns < KTOP && remaining > 0) {
        int M = remaining < CHUNK ? remaining : CHUNK;

        // ---- two-level 8-bit histogram pivot --------------------------------
        unsigned pivot = 0;
        int needed = M;
        #pragma unroll
        for (int level = 0; level < 2; level++) {
            int shift = 24 - 8 * level;
            hist[t] = 0;
            if (t == 0) { s_bin = 0; s_high = 0; }
            __syncthreads();
            #pragma unroll
            for (int j = 0; j < 10; j++) {
                unsigned k = kreg[j];
                bool match = (k != 0u) &&
                    (level == 0 || (k >> 24) == (pivot >> 24));
                if (match) atomicAdd(&hist[(k >> shift) & 255], 1);
            }
            __syncthreads();
            if (t < 32) {
                int s = 0;
                #pragma unroll
                for (int q = 0; q < 8; q++) s += hist[t * 8 + q];
                int suf = s;
                #pragma unroll
                for (int off = 1; off < 32; off <<= 1) {
                    int v = __shfl_down_sync(0xffffffffu, suf, off);
                    if (t + off < 32) suf += v;
                }
                int suf_next = suf - s;
                if (suf >= needed && suf_next < needed) {
                    int cum = suf_next;
                    #pragma unroll
                    for (int q = 7; q >= 0; q--) {
                        int h = hist[t * 8 + q];
                        if (cum + h >= needed) { s_bin = t * 8 + q; s_high = cum; break; }
                        cum += h;
                    }
                }
            }
            __syncthreads();
            pivot |= ((unsigned)s_bin) << shift;
            needed -= s_high;
            __syncthreads();
        }

        // ---- compact all keys >= pivot (zeroed keys are < pivot) -----------
        if (t == 0) sL = 0;
        __syncthreads();
        #pragma unroll
        for (int j = 0; j < 10; j++) {
            unsigned k = kreg[j];
            if (k >= pivot) {
                int p = atomicAdd(&sL, 1);
                if (p < CHCAP)
                    ukey[p] = ((unsigned long long)k << 32) | (unsigned)(4095 - (j * 256 + t));
            }
        }
        __syncthreads();
        int Ltrue = sL;
        int L = Ltrue < CHCAP ? Ltrue : CHCAP;

        // ---- rank sort: only threads t < L rank (idle warps branch around) --
        if (t < L) {
            unsigned long long k0 = ukey[t];
            int r0 = 0;
            for (int q = 0; q < L; q++) r0 += (ukey[q] > k0);   // broadcast LDS
            skey[r0] = k0;   // ranks are a permutation of [0,L)
        }
        __syncthreads();

        // ---- gather boxes in sorted order -----------------------------------
        if (t < L) {
            int i = 4095 - (int)(unsigned)(skey[t] & 0xffffffffull);
            float4 bx = boxes[i];
            cb[t] = bx;
            car[t] = (bx.z - bx.x) * (bx.w - bx.y);
        }
        __syncthreads();

        // ---- tile loop -------------------------------------------------------
        for (int p0 = 0; p0 < L && ns < KTOP; p0 += 32) {
            int nt = L - p0; if (nt > 32) nt = 32;

            // Phase A: suppression by accepted (lane = candidate; warp strides accepted)
            bool sup = false;
            float4 bj = make_float4(0.f, 0.f, 0.f, 0.f); float aj = 0.f;
            bool jok = lane < nt;
            if (jok) { bj = cb[p0 + lane]; aj = car[p0 + lane]; }
            for (int a = wid; a < ns; a += 8) {
                float4 ba = ab[a];
                float yy1 = fmaxf(ba.x, bj.x);
                float xx1 = fmaxf(ba.y, bj.y);
                float yy2 = fminf(ba.z, bj.z);
                float xx2 = fminf(ba.w, bj.w);
                float inter = fmaxf(yy2 - yy1, 0.f) * fmaxf(xx2 - xx1, 0.f);
                float iou = inter / (aar_[a] + aj - inter + 1e-9f);
                sup |= (jok && iou > 0.5f);
            }
            unsigned bal = __ballot_sync(0xffffffffu, sup);
            if (lane == 0) wsup[wid] = bal;

            // Phase B: intra-tile triangular matrix, warp w rows i = w, w+8, ...
            #pragma unroll
            for (int ii = 0; ii < 4; ii++) {
                int i = wid + ii * 8;
                bool s = false;
                if (i < nt) {
                    float4 bi = cb[p0 + i];
                    float ai = car[p0 + i];
                    if (jok && lane > i) {
                        float yy1 = fmaxf(bi.x, bj.x);
                        float xx1 = fmaxf(bi.y, bj.y);
                        float yy2 = fminf(bi.z, bj.z);
                        float xx2 = fminf(bi.w, bj.w);
                        float inter = fmaxf(yy2 - yy1, 0.f) * fmaxf(xx2 - xx1, 0.f);
                        float iou = inter / (ai + aj - inter + 1e-9f);
                        s = iou > 0.5f;
                    }
                }
                unsigned mb = __ballot_sync(0xffffffffu, s);
                if (lane == 0 && i < 32) mat32[i] = mb;
            }
            __syncthreads();

            // Phase C: serial bit-scan (thread 0)
            if (t == 0) {
                unsigned alive = ~(wsup[0] | wsup[1] | wsup[2] | wsup[3] |
                                   wsup[4] | wsup[5] | wsup[6] | wsup[7]);
                if (nt < 32) alive &= ((1u << nt) - 1u);
                unsigned accm = 0; int n2 = ns;
                while (alive && n2 < KTOP) {
                    int i = __ffs(alive) - 1;
                    accm |= (1u << i);
                    n2++;
                    alive &= ~(1u << i);
                    alive &= ~mat32[i];
                }
                s_accmask = accm; s_ns = n2;
            }
            __syncthreads();

            // Phase D: parallel append of accepted
            unsigned accm = s_accmask;
            if (t < 32 && ((accm >> t) & 1u)) {
                int r = ns + __popc(accm & ((1u << t) - 1u));
                unsigned long long key = skey[p0 + t];
                selS[r] = u2f((unsigned)(key >> 32));
                selI[r] = 4095 - (int)(unsigned)(key & 0xffffffffull);
                ab[r] = cb[p0 + t];
                aar_[r] = car[p0 + t];
            }
            __syncthreads();
            ns = s_ns;
        }

        // ---- zero consumed keys; update remaining ----------------------------
        #pragma unroll
        for (int j = 0; j < 10; j++)
            if (kreg[j] >= pivot) kreg[j] = 0u;
        remaining -= Ltrue;
    }
    // fewer than KTOP survivors: reference yields argmax over all -inf
    for (int r = ns + t; r < KTOP; r += 256) { selS[r] = -INFINITY; selI[r] = 0; }
}

// -------- K4: per-batch final top-100 (2-level histogram) + masking ---------
__global__ void __launch_bounds__(256) k_final(float* __restrict__ out) {
    __shared__ int hist[256];
    __shared__ int s_bin, s_high;
    __shared__ int sL;
    __shared__ unsigned long long fukey[384];
    __shared__ unsigned long long fskey[384];
    const int N2 = NCLS * KTOP;   // 2000
    int b = blockIdx.x, t = threadIdx.x;
    const float* sel = g_selscore + (size_t)b * N2;

    pdl_wait();   // g_selscore/g_selidx must be complete (k_nms)

    unsigned fk[8];
    #pragma unroll
    for (int j = 0; j < 8; j++) {
        int i = j * 256 + t;
        unsigned k = 0u;
        if (i < N2) {
            float s = sel[i];
            if (isfinite(s)) k = f2u(s);
        }
        fk[j] = k;
    }
    // two-level histogram pivot for rank KTOP
    unsigned pivot = 0;
    int needed = KTOP;
    #pragma unroll
    for (int level = 0; level < 2; level++) {
        int shift = 24 - 8 * level;
        hist[t] = 0;
        if (t == 0) { s_bin = 0; s_high = 0; }
        __syncthreads();
        #pragma unroll
        for (int j = 0; j < 8; j++) {
            unsigned k = fk[j];
            bool match = (k != 0u) && (level == 0 || (k >> 24) == (pivot >> 24));
            if (match) atomicAdd(&hist[(k >> shift) & 255], 1);
        }
        __syncthreads();
        if (t < 32) {
            int s = 0;
            #pragma unroll
            for (int q = 0; q < 8; q++) s += hist[t * 8 + q];
            int suf = s;
            #pragma unroll
            for (int off = 1; off < 32; off <<= 1) {
                int v = __shfl_down_sync(0xffffffffu, suf, off);
                if (t + off < 32) suf += v;
            }
            int suf_next = suf - s;
            if (suf >= needed && suf_next < needed) {
                int cum = suf_next;
                #pragma unroll
                for (int q = 7; q >= 0; q--) {
                    int h = hist[t * 8 + q];
                    if (cum + h >= needed) { s_bin = t * 8 + q; s_high = cum; break; }
                    cum += h;
                }
            }
        }
        __syncthreads();
        pivot |= ((unsigned)s_bin) << shift;
        needed -= s_high;
        __syncthreads();
    }
    // compact finite keys >= pivot (prefix-complete incl. ties)
    if (t == 0) sL = 0;
    __syncthreads();
    #pragma unroll
    for (int j = 0; j < 8; j++) {
        int i = j * 256 + t;
        unsigned k = fk[j];
        if (k != 0u && k >= pivot) {
            int p = atomicAdd(&sL, 1);
            if (p < 384) fukey[p] = ((unsigned long long)k << 32) | (unsigned)(4095 - i);
        }
    }
    for (int p = t; p < 384; p += 256) fskey[p] = 0ull;
    __syncthreads();
    int L2 = sL < 384 ? sL : 384;
    {
        unsigned long long k0 = 0ull, k1 = 0ull;
        int p0i = t, p1i = t + 256;
        if (p0i < L2) k0 = fukey[p0i];
        if (p1i < L2) k1 = fukey[p1i];
        int r0 = 0, r1 = 0;
        for (int q = 0; q < L2; q++) {
            unsigned long long kq = fukey[q];
            r0 += (kq > k0);
            r1 += (kq > k1);
        }
        __syncthreads();
        if (p0i < L2 && r0 < 384) fskey[r0] = k0;
        if (p1i < L2 && r1 < 384) fskey[r1] = k1;
    }
    __syncthreads();
    if (t < KTOP) {
        unsigned long long key = fskey[t];
        float* o = out + ((size_t)b * KTOP + t) * 6;
        float vals[6] = {0.f, 0.f, 0.f, 0.f, 0.f, 0.f};
        if (key != 0ull) {
            int i = 4095 - (int)(unsigned)(key & 0xffffffffull);
            int cc = i / KTOP, kk = i % KTOP;
            float s = g_selscore[((size_t)b * NCLS + cc) * KTOP + kk];
            if (isfinite(s) && s > 0.3f) {
                int idx = g_selidx[((size_t)b * NCLS + cc) * KTOP + kk];
                float4 bx = g_boxes[b * NSEL + idx];
                vals[0] = bx.x; vals[1] = bx.y; vals[2] = bx.z; vals[3] = bx.w;
                vals[4] = s; vals[5] = (float)cc;
            }
        }
        #pragma unroll
        for (int q = 0; q < 6; q++) o[q] = vals[q];
    }
}

// ---------------- launch (PDL-chained) ---------------------------------------
static void launch_pdl(void* func, dim3 grid, dim3 block, void** args) {
    cudaLaunchConfig_t cfg = {};
    cfg.gridDim = grid;
    cfg.blockDim = block;
    cfg.dynamicSmemBytes = 0;
    cfg.stream = 0;
    cudaLaunchAttribute attr[1];
    attr[0].id = cudaLaunchAttributeProgrammaticStreamSerialization;
    attr[0].val.programmaticStreamSerializationAllowed = 1;
    cfg.attrs = attr;
    cfg.numAttrs = 1;
    cudaLaunchKernelExC(&cfg, func, args);
}

extern "C" void kernel_launch(void* const* d_in, const int* in_sizes, int n_in,
                              void* d_out, int out_size) {
    const float *cls0 = 0, *cls1 = 0, *cls2 = 0, *bb0 = 0, *bb1 = 0, *bb2 = 0;
    for (int i = 0; i < n_in; i++) {
        const float* p = (const float*)d_in[i];
        switch (in_sizes[i]) {
            case 2048000: cls0 = p; break;  // 16*6400*20
            case 3276800: bb0  = p; break;  // 16*6400*32
            case 512000:  cls1 = p; break;  // 16*1600*20
            case 819200:  bb1  = p; break;  // 16*1600*32
            case 128000:  cls2 = p; break;  // 16*400*20
            case 204800:  bb2  = p; break;  // 16*400*32
            default: break;                 // origin_shapes (unused by reference)
        }
    }
    k_select<<<32, 1024>>>(cls0, cls1);

    {
        void* args[6] = {&cls0, &cls1, &cls2, &bb0, &bb1, &bb2};
        launch_pdl((void*)k_gather, dim3(BATCH * 10), dim3(256), args);
    }
    {
        void* args[1] = {nullptr};
        launch_pdl((void*)k_nms, dim3(BATCH * NCLS), dim3(256), args);
    }
    {
        float* outp = (float*)d_out;
        void* args[1] = {&outp};
        launch_pdl((void*)k_final, dim3(BATCH), dim3(256), args);
    }
}